// round 14
// baseline (speedup 1.0000x reference)
#include <cuda_runtime.h>
#include <cuda_fp16.h>
#include <cstdint>

#define NT   448                   // 14 warps: 7 o-groups (32 rows) x 2 d-halves (32 d)
#define SKC  64                    // superchunk k extent
#define TSZ  8192                  // 64 rows x 128B, one T superchunk tile

// smem byte map
#define OFF_V  0                   // v: 2560 f32 (stride 64)        = 10240
#define OFF_H  10240               // h: 100 x 72 f32 (padded)       = 28800
#define OFF_T  39040               // 2 x TSZ (128B aligned)
#define OFF_PS (OFF_T + 2*TSZ)     // psum: 224 f32 = 896B
#define SMEM_BYTES (OFF_PS + 896)  // 56320  (x2 CTA = 112640 <= 228KB)

// Pre-arranged W in A-fragment order:
// g_wf[sc][otile 0..13][kq 0..3][lane] = uint4{a0,a1,a2,a3} for m16n8k16 A of
// rows otile*16..+16, k = sc*64+kq*16. Out-of-range rows/k are zero.
__device__ uint4 g_wf[151 * 1792];

static __device__ __forceinline__ uint32_t smem_u32(const void* p) {
    uint32_t a;
    asm("{ .reg .u64 t; cvta.to.shared.u64 t, %1; cvt.u32.u64 %0, t; }" : "=r"(a) : "l"(p));
    return a;
}
static __device__ __forceinline__ void sts128(uint32_t a, uint4 v) {
    asm volatile("st.shared.v4.b32 [%0], {%1,%2,%3,%4};"
                 :: "r"(a), "r"(v.x), "r"(v.y), "r"(v.z), "r"(v.w));
}
static __device__ __forceinline__ void ldsm4(uint32_t& r0, uint32_t& r1,
                                             uint32_t& r2, uint32_t& r3, uint32_t a) {
    asm volatile("ldmatrix.sync.aligned.m8n8.x4.shared.b16 {%0,%1,%2,%3}, [%4];"
                 : "=r"(r0), "=r"(r1), "=r"(r2), "=r"(r3) : "r"(a));
}
static __device__ __forceinline__ void mma16816(float* c, uint32_t a0, uint32_t a1,
                                                uint32_t a2, uint32_t a3,
                                                uint32_t b0, uint32_t b1) {
    asm volatile(
        "mma.sync.aligned.m16n8k16.row.col.f32.f16.f16.f32 "
        "{%0,%1,%2,%3}, {%4,%5,%6,%7}, {%8,%9}, {%0,%1,%2,%3};"
        : "+f"(c[0]), "+f"(c[1]), "+f"(c[2]), "+f"(c[3])
        : "r"(a0), "r"(a1), "r"(a2), "r"(a3), "r"(b0), "r"(b1));
}
static __device__ __forceinline__ uint32_t h2u(__half2 h) {
    return *reinterpret_cast<uint32_t*>(&h);
}

// ---- prep: W fp32 -> fp16 A-fragment-ordered global tiles (14 o-tiles), zero-pad ----
__global__ void _CIN_prep_kernel(const float* __restrict__ w1,
                                 const float* __restrict__ w2,
                                 const float* __restrict__ w3) {
    int sc = blockIdx.x;           // global superchunk 0..150
    const float* W; int K, scl;
    if (sc < 25)      { W = w1; K = 1600; scl = sc; }
    else if (sc < 88) { W = w2; K = 4000; scl = sc - 25; }
    else              { W = w3; K = 4000; scl = sc - 88; }
    const int kbase = scl * SKC;
    uint4* dst = g_wf + (size_t)sc * 1792;
    for (int idx = threadIdx.x; idx < 1792; idx += 256) {  // 14 ot x 4 kq x 32 lanes
        const int lane = idx & 31, kq = (idx >> 5) & 3, ot = idx >> 7;
        const int g = lane >> 2, tig = lane & 3;
        const int r0 = ot*16 + g, r1 = r0 + 8;
        const int k = kbase + kq*16 + 2*tig;
        uint4 val = make_uint4(0, 0, 0, 0);
        if (k < K) {
            if (r0 < 200) {
                const float* s = W + r0*K + k;
                val.x = h2u(__floats2half2_rn(s[0], s[1]));
                val.z = h2u(__floats2half2_rn(s[8], s[9]));
            }
            if (r1 < 200) {
                const float* s = W + r1*K + k;
                val.y = h2u(__floats2half2_rn(s[0], s[1]));
                val.w = h2u(__floats2half2_rn(s[8], s[9]));
            }
        }
        dst[idx] = val;
    }
}

// ---- T superchunk build: 512 tasks of (d, 8k) ----
template<int K, int Nh, int SRCS>
static __device__ __forceinline__ void build_T(const float* __restrict__ v,
                                               const float* __restrict__ src,
                                               uint32_t tbase, int k0, int tid) {
    for (int i = tid; i < 512; i += NT) {     // task = (d, q8)
        const int d = i & 63, q8 = i >> 6;
        const int kb = k0 + q8*8;
        if (kb >= K) continue;                // zero-padded W covers the tail
        int m = kb / Nh;
        int n = kb - m*Nh;
        float vm = v[m*64 + d];
        float p[8];
        #pragma unroll
        for (int t = 0; t < 8; t++) {
            if (n == Nh) { n = 0; m++; vm = v[m*64 + d]; }
            p[t] = vm * src[n*SRCS + d];
            n++;
        }
        uint4 q;
        q.x = h2u(__floats2half2_rn(p[0], p[1]));
        q.y = h2u(__floats2half2_rn(p[2], p[3]));
        q.z = h2u(__floats2half2_rn(p[4], p[5]));
        q.w = h2u(__floats2half2_rn(p[6], p[7]));
        const uint32_t sw = ((uint32_t)(d & 7)) << 4;
        sts128(tbase + d*128 + (((uint32_t)(q8*16)) ^ sw), q);
    }
}

// ---- one layer ----
template<int K, int Nh, int SRCS, int SC0, int NSC, int OUT_OFF, bool LAST>
static __device__ __forceinline__ void layer_run(
    const float* __restrict__ bg, char* smem, uint32_t smem_base,
    float* __restrict__ out, int b, int tid)
{
    const float* v   = reinterpret_cast<const float*>(smem + OFF_V);
    const float* src = (Nh == 40) ? v : reinterpret_cast<const float*>(smem + OFF_H);
    float* h  = reinterpret_cast<float*>(smem + OFF_H);
    float* ps = reinterpret_cast<float*>(smem + OFF_PS);

    const int lane = tid & 31, w = tid >> 5;
    const int g = lane >> 2, tig = lane & 3;
    const int og = w % 7, dg = w / 7;        // o-group (32 rows), d-half (32 d)
    const int o0 = og * 32;

    // ldmatrix lane decomposition (B): tiles = 2 d-subtiles x 2 k-halves
    const int lt = lane >> 3, lr = lane & 7;
    const uint32_t lsw = ((uint32_t)lr) << 4;
    const uint32_t bRowB = (uint32_t)(dg*32 + (lt >> 1)*8 + lr) * 128;
    const uint32_t bColH = (uint32_t)(lt & 1) * 16;

    float c[2][4][4];   // 32 acc: [ot][jj (d-subtile)][frag]
    #pragma unroll
    for (int ot = 0; ot < 2; ot++)
        #pragma unroll
        for (int j = 0; j < 4; j++)
            #pragma unroll
            for (int r = 0; r < 4; r++) c[ot][j][r] = 0.0f;

    // stage T superchunk 0
    build_T<K, Nh, SRCS>(v, src, smem_base + OFF_T, 0, tid);
    __syncthreads();

    // per-warp A fragment streams (coalesced LDG.128, L1D-cached)
    const uint4* A0 = g_wf + (size_t)SC0*1792 + (size_t)(og*2    )*128 + lane;
    const uint4* A1 = g_wf + (size_t)SC0*1792 + (size_t)(og*2 + 1)*128 + lane;

    for (int sc = 0; sc < NSC; sc++) {
        const int cur = sc & 1, nxt = cur ^ 1;
        const bool more = (sc + 1) < NSC;

        // producer first: T build for next superchunk (overlaps MMA issue)
        if (more)
            build_T<K, Nh, SRCS>(v, src, smem_base + OFF_T + nxt*TSZ, (sc + 1)*SKC, tid);

        // MMA: 4 kq x (2 LDG.128 A + 2 B-ldsm + 8 MMA)
        const uint32_t Tb = smem_base + OFF_T + cur*TSZ + bRowB;
        const size_t scoff = (size_t)sc * 1792;
        #pragma unroll
        for (int kq = 0; kq < 4; kq++) {
            const uint4 a0 = __ldg(A0 + scoff + kq*32);
            const uint4 a1 = __ldg(A1 + scoff + kq*32);
            const uint32_t bCol = (((uint32_t)(kq*32) + bColH) ^ lsw);
            #pragma unroll
            for (int i = 0; i < 2; i++) {     // d-subtile pair i: d = dg*32 + i*16
                uint32_t b0, b1, b2, b3;
                ldsm4(b0, b1, b2, b3, Tb + (uint32_t)i*2048 + bCol);
                mma16816(c[0][2*i],   a0.x, a0.y, a0.z, a0.w, b0, b1);
                mma16816(c[0][2*i+1], a0.x, a0.y, a0.z, a0.w, b2, b3);
                mma16816(c[1][2*i],   a1.x, a1.y, a1.z, a1.w, b0, b1);
                mma16816(c[1][2*i+1], a1.x, a1.y, a1.z, a1.w, b2, b3);
            }
        }
        __syncthreads();
    }

    // epilogue: bias+relu, h write (own 32-d slice), partial d-sums via smem
    float sA[2], sB[2];   // per ot: row r0 and r1 partial sums over this warp's 32 d
    #pragma unroll
    for (int ot = 0; ot < 2; ot++) {
        const int r0 = o0 + ot*16 + g, r1 = r0 + 8;
        const float bz0 = (r0 < 200) ? bg[r0] : 0.0f;
        const float bz1 = (r1 < 200) ? bg[r1] : 0.0f;
        float s0 = 0.0f, s1 = 0.0f;
        #pragma unroll
        for (int j = 0; j < 4; j++) {
            float y00 = fmaxf(c[ot][j][0] + bz0, 0.0f);
            float y01 = fmaxf(c[ot][j][1] + bz0, 0.0f);
            float y10 = fmaxf(c[ot][j][2] + bz1, 0.0f);
            float y11 = fmaxf(c[ot][j][3] + bz1, 0.0f);
            if (!LAST) {
                const int d = dg*32 + j*8 + 2*tig;
                if (r0 < 100) *reinterpret_cast<float2*>(h + r0*72 + d) = make_float2(y00, y01);
                if (r1 < 100) *reinterpret_cast<float2*>(h + r1*72 + d) = make_float2(y10, y11);
            }
            s0 += y00 + y01;
            s1 += y10 + y11;
        }
        s0 += __shfl_xor_sync(0xFFFFFFFFu, s0, 1);
        s0 += __shfl_xor_sync(0xFFFFFFFFu, s0, 2);
        s1 += __shfl_xor_sync(0xFFFFFFFFu, s1, 1);
        s1 += __shfl_xor_sync(0xFFFFFFFFu, s1, 2);
        sA[ot] = s0; sB[ot] = s1;
    }
    if (dg == 0 && tig == 0) {
        #pragma unroll
        for (int ot = 0; ot < 2; ot++) {
            ps[o0 + ot*16 + g]     = sA[ot];
            ps[o0 + ot*16 + g + 8] = sB[ot];
        }
    }
    __syncthreads();   // also orders h writes before next layer's build_T reads
    if (dg == 1 && tig == 0) {
        #pragma unroll
        for (int ot = 0; ot < 2; ot++) {
            const int r0 = o0 + ot*16 + g, r1 = r0 + 8;
            const float t0 = sA[ot] + ps[r0];
            const float t1 = sB[ot] + ps[r1];
            if (LAST) {
                if (r0 < 200) out[b*400 + 200 + r0] = t0;
                if (r1 < 200) out[b*400 + 200 + r1] = t1;
            } else {
                if (r0 >= 100 && r0 < 200) out[b*400 + OUT_OFF + (r0 - 100)] = t0;
                if (r1 >= 100 && r1 < 200) out[b*400 + OUT_OFF + (r1 - 100)] = t1;
            }
        }
    }
    __syncthreads();   // psum stable before any reuse; T buffers free
}

__global__ void __launch_bounds__(NT, 2)
_CIN_41575283425691_kernel(const float* __restrict__ x,
                           const float* __restrict__ b1,
                           const float* __restrict__ b2,
                           const float* __restrict__ b3,
                           float* __restrict__ out)
{
    extern __shared__ char smem[];
    const uint32_t smem_base = smem_u32(smem);
    const int tid = threadIdx.x;
    const int b   = blockIdx.x;

    float* v = reinterpret_cast<float*>(smem + OFF_V);
    const float* xb = x + b*2560;
    for (int i = tid; i < 2560; i += NT) v[i] = xb[i];
    __syncthreads();

    layer_run<1600,  40, 64,  0, 25,   0, false>(b1, smem, smem_base, out, b, tid);
    layer_run<4000, 100, 72, 25, 63, 100, false>(b2, smem, smem_base, out, b, tid);
    layer_run<4000, 100, 72, 88, 63,   0, true >(b3, smem, smem_base, out, b, tid);
}

extern "C" void kernel_launch(void* const* d_in, const int* in_sizes, int n_in,
                              void* d_out, int out_size)
{
    const float* x  = (const float*)d_in[0];
    const float* w1 = (const float*)d_in[1];
    const float* b1 = (const float*)d_in[2];
    const float* w2 = (const float*)d_in[3];
    const float* b2 = (const float*)d_in[4];
    const float* w3 = (const float*)d_in[5];
    const float* b3 = (const float*)d_in[6];
    float* out = (float*)d_out;

    _CIN_prep_kernel<<<151, 256>>>(w1, w2, w3);

    cudaFuncSetAttribute(_CIN_41575283425691_kernel,
                         cudaFuncAttributeMaxDynamicSharedMemorySize, SMEM_BYTES);
    _CIN_41575283425691_kernel<<<512, NT, SMEM_BYTES>>>(x, b1, b2, b3, out);
}

// round 15
// speedup vs baseline: 1.0837x; 1.0837x over previous
#include <cuda_runtime.h>
#include <cuda_fp16.h>
#include <cstdint>

#define NT   224                   // 7 warps, each 32 o-rows x 64 d
#define SKC  64                    // superchunk k extent
#define TSZ  8192                  // 64 rows x 128B, one T superchunk tile

// smem byte map
#define OFF_V  0                   // v: 2560 f32 (stride 64)        = 10240
#define OFF_H  10240               // h: 100 x 72 f32 (padded)       = 28800
#define OFF_T  39040               // 2 x TSZ (128B aligned)
#define SMEM_BYTES (OFF_T + 2*TSZ) // 55424  (x2 CTA = 110848 <= 228KB)

// Pre-arranged W in A-fragment order:
// g_wf[sc][otile 0..13][kq 0..3][lane] = uint4{a0,a1,a2,a3} for m16n8k16 A of
// rows otile*16..+16, k = sc*64+kq*16. Out-of-range rows/k are zero.
__device__ uint4 g_wf[151 * 1792];

static __device__ __forceinline__ uint32_t smem_u32(const void* p) {
    uint32_t a;
    asm("{ .reg .u64 t; cvta.to.shared.u64 t, %1; cvt.u32.u64 %0, t; }" : "=r"(a) : "l"(p));
    return a;
}
static __device__ __forceinline__ void sts128(uint32_t a, uint4 v) {
    asm volatile("st.shared.v4.b32 [%0], {%1,%2,%3,%4};"
                 :: "r"(a), "r"(v.x), "r"(v.y), "r"(v.z), "r"(v.w));
}
static __device__ __forceinline__ void ldsm4(uint32_t& r0, uint32_t& r1,
                                             uint32_t& r2, uint32_t& r3, uint32_t a) {
    asm volatile("ldmatrix.sync.aligned.m8n8.x4.shared.b16 {%0,%1,%2,%3}, [%4];"
                 : "=r"(r0), "=r"(r1), "=r"(r2), "=r"(r3) : "r"(a));
}
static __device__ __forceinline__ void mma16816(float* c, uint32_t a0, uint32_t a1,
                                                uint32_t a2, uint32_t a3,
                                                uint32_t b0, uint32_t b1) {
    asm volatile(
        "mma.sync.aligned.m16n8k16.row.col.f32.f16.f16.f32 "
        "{%0,%1,%2,%3}, {%4,%5,%6,%7}, {%8,%9}, {%0,%1,%2,%3};"
        : "+f"(c[0]), "+f"(c[1]), "+f"(c[2]), "+f"(c[3])
        : "r"(a0), "r"(a1), "r"(a2), "r"(a3), "r"(b0), "r"(b1));
}
static __device__ __forceinline__ uint32_t h2u(__half2 h) {
    return *reinterpret_cast<uint32_t*>(&h);
}

// ---- prep: W fp32 -> fp16 A-fragment-ordered global tiles (14 o-tiles), zero-pad ----
__global__ void _CIN_prep_kernel(const float* __restrict__ w1,
                                 const float* __restrict__ w2,
                                 const float* __restrict__ w3) {
    int sc = blockIdx.x;           // global superchunk 0..150
    const float* W; int K, scl;
    if (sc < 25)      { W = w1; K = 1600; scl = sc; }
    else if (sc < 88) { W = w2; K = 4000; scl = sc - 25; }
    else              { W = w3; K = 4000; scl = sc - 88; }
    const int kbase = scl * SKC;
    uint4* dst = g_wf + (size_t)sc * 1792;
    for (int idx = threadIdx.x; idx < 1792; idx += 256) {  // 14 ot x 4 kq x 32 lanes
        const int lane = idx & 31, kq = (idx >> 5) & 3, ot = idx >> 7;
        const int g = lane >> 2, tig = lane & 3;
        const int r0 = ot*16 + g, r1 = r0 + 8;
        const int k = kbase + kq*16 + 2*tig;
        uint4 val = make_uint4(0, 0, 0, 0);
        if (k < K) {
            if (r0 < 200) {
                const float* s = W + r0*K + k;
                val.x = h2u(__floats2half2_rn(s[0], s[1]));
                val.z = h2u(__floats2half2_rn(s[8], s[9]));
            }
            if (r1 < 200) {
                const float* s = W + r1*K + k;
                val.y = h2u(__floats2half2_rn(s[0], s[1]));
                val.w = h2u(__floats2half2_rn(s[8], s[9]));
            }
        }
        dst[idx] = val;
    }
}

// ---- T superchunk build: 512 tasks of (d, 8k) ----
template<int K, int Nh, int SRCS>
static __device__ __forceinline__ void build_T(const float* __restrict__ v,
                                               const float* __restrict__ src,
                                               uint32_t tbase, int k0, int tid) {
    for (int i = tid; i < 512; i += NT) {     // task = (d, q8)
        const int d = i & 63, q8 = i >> 6;
        const int kb = k0 + q8*8;
        if (kb >= K) continue;                // zero-padded W covers the tail
        int m = kb / Nh;
        int n = kb - m*Nh;
        float vm = v[m*64 + d];
        float p[8];
        #pragma unroll
        for (int t = 0; t < 8; t++) {
            if (n == Nh) { n = 0; m++; vm = v[m*64 + d]; }
            p[t] = vm * src[n*SRCS + d];
            n++;
        }
        uint4 q;
        q.x = h2u(__floats2half2_rn(p[0], p[1]));
        q.y = h2u(__floats2half2_rn(p[2], p[3]));
        q.z = h2u(__floats2half2_rn(p[4], p[5]));
        q.w = h2u(__floats2half2_rn(p[6], p[7]));
        const uint32_t sw = ((uint32_t)(d & 7)) << 4;
        sts128(tbase + d*128 + (((uint32_t)(q8*16)) ^ sw), q);
    }
}

// ---- one layer ----
template<int K, int Nh, int SRCS, int SC0, int NSC, int OUT_OFF, bool LAST>
static __device__ __forceinline__ void layer_run(
    const float* __restrict__ bg, char* smem, uint32_t smem_base,
    float* __restrict__ out, int b, int tid)
{
    const float* v   = reinterpret_cast<const float*>(smem + OFF_V);
    const float* src = (Nh == 40) ? v : reinterpret_cast<const float*>(smem + OFF_H);
    float* h = reinterpret_cast<float*>(smem + OFF_H);

    const int lane = tid & 31, w = tid >> 5;   // w = 0..6, o-rows [w*32, w*32+32)
    const int g = lane >> 2, tig = lane & 3;
    const int o0 = w * 32;

    // ldmatrix lane decomposition (B): 2 d-subtiles x 2 k-halves per ldsm4
    const int lt = lane >> 3, lr = lane & 7;
    const uint32_t lsw = ((uint32_t)lr) << 4;
    const uint32_t bRowB = (uint32_t)((lt >> 1)*8 + lr) * 128;
    const uint32_t bColH = (uint32_t)(lt & 1) * 16;

    float c[2][8][4];   // 64 acc: [ot][j (d-tile)][frag]
    #pragma unroll
    for (int ot = 0; ot < 2; ot++)
        #pragma unroll
        for (int j = 0; j < 8; j++)
            #pragma unroll
            for (int r = 0; r < 4; r++) c[ot][j][r] = 0.0f;

    // stage T superchunk 0
    build_T<K, Nh, SRCS>(v, src, smem_base + OFF_T, 0, tid);
    __syncthreads();

    // per-warp A fragment streams (coalesced LDG.128, L1D-cached, shared by both CTAs)
    const uint4* A0 = g_wf + (size_t)SC0*1792 + (size_t)(w*2    )*128 + lane;
    const uint4* A1 = g_wf + (size_t)SC0*1792 + (size_t)(w*2 + 1)*128 + lane;

    for (int sc = 0; sc < NSC; sc++) {
        const int cur = sc & 1, nxt = cur ^ 1;
        const bool more = (sc + 1) < NSC;

        // producer first: T build for next superchunk (overlaps MMA issue)
        if (more)
            build_T<K, Nh, SRCS>(v, src, smem_base + OFF_T + nxt*TSZ, (sc + 1)*SKC, tid);

        // MMA: 4 kq x (2 LDG.128 A + 4 B-ldsm + 16 MMA)
        const uint32_t Tb = smem_base + OFF_T + cur*TSZ + bRowB;
        const size_t scoff = (size_t)sc * 1792;
        #pragma unroll
        for (int kq = 0; kq < 4; kq++) {
            const uint4 a0 = __ldg(A0 + scoff + kq*32);
            const uint4 a1 = __ldg(A1 + scoff + kq*32);
            const uint32_t bCol = (((uint32_t)(kq*32) + bColH) ^ lsw);
            #pragma unroll
            for (int jj = 0; jj < 4; jj++) {   // d-subtile pair jj: d = jj*16
                uint32_t b0, b1, b2, b3;
                ldsm4(b0, b1, b2, b3, Tb + (uint32_t)jj*2048 + bCol);
                mma16816(c[0][2*jj],   a0.x, a0.y, a0.z, a0.w, b0, b1);
                mma16816(c[0][2*jj+1], a0.x, a0.y, a0.z, a0.w, b2, b3);
                mma16816(c[1][2*jj],   a1.x, a1.y, a1.z, a1.w, b0, b1);
                mma16816(c[1][2*jj+1], a1.x, a1.y, a1.z, a1.w, b2, b3);
            }
        }
        __syncthreads();
    }

    // epilogue: bias+relu, h write, full in-warp d-sum
    #pragma unroll
    for (int ot = 0; ot < 2; ot++) {
        const int r0 = o0 + ot*16 + g, r1 = r0 + 8;
        const float bz0 = (r0 < 200) ? bg[r0] : 0.0f;
        const float bz1 = (r1 < 200) ? bg[r1] : 0.0f;
        float s0 = 0.0f, s1 = 0.0f;
        #pragma unroll
        for (int j = 0; j < 8; j++) {
            float y00 = fmaxf(c[ot][j][0] + bz0, 0.0f);
            float y01 = fmaxf(c[ot][j][1] + bz0, 0.0f);
            float y10 = fmaxf(c[ot][j][2] + bz1, 0.0f);
            float y11 = fmaxf(c[ot][j][3] + bz1, 0.0f);
            if (!LAST) {
                const int d = j*8 + 2*tig;
                if (r0 < 100) *reinterpret_cast<float2*>(h + r0*72 + d) = make_float2(y00, y01);
                if (r1 < 100) *reinterpret_cast<float2*>(h + r1*72 + d) = make_float2(y10, y11);
            }
            s0 += y00 + y01;
            s1 += y10 + y11;
        }
        s0 += __shfl_xor_sync(0xFFFFFFFFu, s0, 1);
        s0 += __shfl_xor_sync(0xFFFFFFFFu, s0, 2);
        s1 += __shfl_xor_sync(0xFFFFFFFFu, s1, 1);
        s1 += __shfl_xor_sync(0xFFFFFFFFu, s1, 2);
        if (tig == 0) {
            if (LAST) {
                if (r0 < 200) out[b*400 + 200 + r0] = s0;
                if (r1 < 200) out[b*400 + 200 + r1] = s1;
            } else {
                if (r0 >= 100 && r0 < 200) out[b*400 + OUT_OFF + (r0 - 100)] = s0;
                if (r1 >= 100 && r1 < 200) out[b*400 + OUT_OFF + (r1 - 100)] = s1;
            }
        }
    }
    __syncthreads();   // h fully written before next layer's build_T reads it
}

__global__ void __launch_bounds__(NT, 2)
_CIN_41575283425691_kernel(const float* __restrict__ x,
                           const float* __restrict__ b1,
                           const float* __restrict__ b2,
                           const float* __restrict__ b3,
                           float* __restrict__ out)
{
    extern __shared__ char smem[];
    const uint32_t smem_base = smem_u32(smem);
    const int tid = threadIdx.x;
    const int b   = blockIdx.x;

    float* v = reinterpret_cast<float*>(smem + OFF_V);
    const float* xb = x + b*2560;
    for (int i = tid; i < 2560; i += NT) v[i] = xb[i];
    __syncthreads();

    layer_run<1600,  40, 64,  0, 25,   0, false>(b1, smem, smem_base, out, b, tid);
    layer_run<4000, 100, 72, 25, 63, 100, false>(b2, smem, smem_base, out, b, tid);
    layer_run<4000, 100, 72, 88, 63,   0, true >(b3, smem, smem_base, out, b, tid);
}

extern "C" void kernel_launch(void* const* d_in, const int* in_sizes, int n_in,
                              void* d_out, int out_size)
{
    const float* x  = (const float*)d_in[0];
    const float* w1 = (const float*)d_in[1];
    const float* b1 = (const float*)d_in[2];
    const float* w2 = (const float*)d_in[3];
    const float* b2 = (const float*)d_in[4];
    const float* w3 = (const float*)d_in[5];
    const float* b3 = (const float*)d_in[6];
    float* out = (float*)d_out;

    _CIN_prep_kernel<<<151, 256>>>(w1, w2, w3);

    cudaFuncSetAttribute(_CIN_41575283425691_kernel,
                         cudaFuncAttributeMaxDynamicSharedMemorySize, SMEM_BYTES);
    _CIN_41575283425691_kernel<<<512, NT, SMEM_BYTES>>>(x, b1, b2, b3, out);
}